// round 13
// baseline (speedup 1.0000x reference)
#include <cuda_runtime.h>
#include <cstdint>

#define B_ 16
#define D_ 16
#define H_ 288
#define W_ 512
#define N_ (H_*W_)   // 147456
#define L_ 17
#define CH_ 64       // k3 chunks -> 2304 px/block
#define SP_ 512      // k1 stage pixels (2KB per bulk copy)
#define K1CH 32      // k1 chunks -> 4608 px/block
#define NST_ ((N_/K1CH)/SP_)   // 9 stages per k1 block

// persistent scratch (re-zeroed every launch: graph replays reuse it)
__device__ float g_sums[B_][L_][D_];
__device__ float g_cnt[B_][L_];
__device__ float g_means[B_][L_][D_];
__device__ float g_w[B_][L_];

__device__ __forceinline__ uint32_t smem_u32(const void* p) {
    uint32_t a;
    asm("{ .reg .u64 t; cvta.to.shared.u64 t, %1; cvt.u32.u64 %0, t; }"
        : "=r"(a) : "l"(p));
    return a;
}

// ---------------------------------------------------------------- kernel 0
__global__ void k0_zero(float* out) {
    int t = blockIdx.x * blockDim.x + threadIdx.x;
    int stride = gridDim.x * blockDim.x;
    if (t == 0) out[0] = 0.f;
    float* s = &g_sums[0][0][0];
    for (int i = t; i < B_*L_*D_; i += stride) s[i] = 0.f;
    float* c = &g_cnt[0][0];
    for (int i = t; i < B_*L_; i += stride) c[i] = 0.f;
}

// ---------------------------------------------------------------- kernel 1
// Per-label sums + counts. Double-buffered cp.async.bulk pipeline with
// 2KB copies (engine fixed-overhead amortized 4x vs 512B): thread 0 issues
// 17 bulk copies (16 dim-rows + seg) per 512-px stage; mbarrier
// expect_tx/complete_tx tracks completion. 8 consumer warps; warp w owns
// dims 2w,2w+1 packed as ONE float2 accumulator per label.
__global__ void __launch_bounds__(256) k1_sums(const float* __restrict__ emb,
                                               const int* __restrict__ seg) {
    __shared__ alignas(16) float sd[2][D_][SP_];   // 64 KB stage data
    __shared__ alignas(16) int   ss[2][SP_];       // 4 KB stage seg
    __shared__ float2 acP[8][32][L_];              // 34.8 KB accumulators
    __shared__ alignas(8) unsigned long long mbar[2];

    const int b    = blockIdx.y;
    const int lane = threadIdx.x;
    const int w    = threadIdx.y;
    const int tid  = w * 32 + lane;
    const int lo   = blockIdx.x * (N_ / K1CH);

    float2* __restrict__ a = &acP[w][lane][0];     // thread-private
#pragma unroll
    for (int s = 0; s < L_; s++) a[s] = make_float2(0.f, 0.f);

    const float* __restrict__ eb = emb + (size_t)b * D_ * N_;
    const int*   __restrict__ sp = seg + (size_t)b * N_;

    const uint32_t mb0 = smem_u32(&mbar[0]);
    const uint32_t mb1 = smem_u32(&mbar[1]);

    if (tid == 0) {
        asm volatile("mbarrier.init.shared.b64 [%0], %1;" :: "r"(mb0), "r"(1) : "memory");
        asm volatile("mbarrier.init.shared.b64 [%0], %1;" :: "r"(mb1), "r"(1) : "memory");
    }
    __syncthreads();

#define ISSUE_STAGE(IT)                                                        \
    {                                                                          \
        int _it  = (IT);                                                       \
        int _buf = _it & 1;                                                    \
        uint32_t _mb = _buf ? mb1 : mb0;                                       \
        asm volatile("mbarrier.arrive.expect_tx.shared.b64 _, [%0], %1;"       \
                     :: "r"(_mb), "r"((uint32_t)(17 * SP_ * 4)) : "memory");   \
        int _base = lo + _it * SP_;                                            \
        _Pragma("unroll")                                                      \
        for (int _d = 0; _d < D_; _d++) {                                      \
            uint32_t _dst = smem_u32(&sd[_buf][_d][0]);                        \
            const void* _src = (const void*)(eb + (size_t)_d * N_ + _base);    \
            asm volatile(                                                      \
                "cp.async.bulk.shared::cta.global.mbarrier::complete_tx::bytes"\
                " [%0], [%1], %2, [%3];"                                       \
                :: "r"(_dst), "l"(_src), "r"((uint32_t)(SP_ * 4)), "r"(_mb)    \
                : "memory");                                                   \
        }                                                                      \
        uint32_t _dst = smem_u32(&ss[_buf][0]);                                \
        const void* _src = (const void*)(sp + _base);                          \
        asm volatile(                                                          \
            "cp.async.bulk.shared::cta.global.mbarrier::complete_tx::bytes"    \
            " [%0], [%1], %2, [%3];"                                           \
            :: "r"(_dst), "l"(_src), "r"((uint32_t)(SP_ * 4)), "r"(_mb)        \
            : "memory");                                                       \
    }

    if (tid == 0) { ISSUE_STAGE(0); ISSUE_STAGE(1); }

    int cnt[16];
#pragma unroll
    for (int l = 0; l < 16; l++) cnt[l] = 0;

    for (int it = 0; it < NST_; ++it) {
        const int buf = it & 1;
        const uint32_t mb = buf ? mb1 : mb0;
        const uint32_t ph = (uint32_t)((it >> 1) & 1);

        // wait for stage data (acquire orders async writes before our LDS)
        {
            uint32_t done;
            asm volatile(
                "{ .reg .pred p;"
                " mbarrier.try_wait.parity.acquire.cta.shared::cta.b64 p, [%1], %2;"
                " selp.b32 %0, 1, 0, p; }"
                : "=r"(done) : "r"(mb), "r"(ph) : "memory");
            while (!done) {
                asm volatile(
                    "{ .reg .pred p;"
                    " mbarrier.try_wait.parity.acquire.cta.shared::cta.b64 p, [%1], %2, 0x989680;"
                    " selp.b32 %0, 1, 0, p; }"
                    : "=r"(done) : "r"(mb), "r"(ph) : "memory");
            }
        }

        // consume 512 px in 4 interleaved groups of 128 px (4 px/lane each)
#pragma unroll
        for (int g = 0; g < 4; g++) {
            const int off = g * 128 + lane * 4;
            int4   s4 = *(const int4*)&ss[buf][off];
            float4 v0 = *(const float4*)&sd[buf][2 * w][off];
            float4 v1 = *(const float4*)&sd[buf][2 * w + 1][off];

            { float2 t = a[s4.x]; t.x += v0.x; t.y += v1.x; a[s4.x] = t; }
            { float2 t = a[s4.y]; t.x += v0.y; t.y += v1.y; a[s4.y] = t; }
            { float2 t = a[s4.z]; t.x += v0.z; t.y += v1.z; a[s4.z] = t; }
            { float2 t = a[s4.w]; t.x += v0.w; t.y += v1.w; a[s4.w] = t; }

            // rotating count warp: each (stage,group) counted exactly once
            if (((it * 4 + g) & 7) == w) {
#pragma unroll
                for (int l = 1; l <= 16; l++)
                    cnt[l-1] += (s4.x == l) + (s4.y == l) + (s4.z == l) + (s4.w == l);
            }
        }

        __syncthreads();                         // buffer free for reissue
        if (tid == 0 && it + 2 < NST_) ISSUE_STAGE(it + 2);
    }
#undef ISSUE_STAGE

    // reduce each thread's private sums across the warp, commit via atomics
#pragma unroll
    for (int s = 1; s < L_; s++) {
        float v0 = a[s].x;
        float v1 = a[s].y;
#pragma unroll
        for (int off = 16; off >= 1; off >>= 1) {
            v0 += __shfl_xor_sync(0xffffffffu, v0, off);
            v1 += __shfl_xor_sync(0xffffffffu, v1, off);
        }
        if (lane == 0) {
            atomicAdd(&g_sums[b][s][2 * w],     v0);
            atomicAdd(&g_sums[b][s][2 * w + 1], v1);
        }
    }
#pragma unroll
    for (int l = 0; l < 16; l++) {
        int c = cnt[l];
#pragma unroll
        for (int off = 16; off >= 1; off >>= 1)
            c += __shfl_xor_sync(0xffffffffu, c, off);
        if (lane == 0 && c > 0) atomicAdd(&g_cnt[b][l+1], (float)c);
    }
}

// ---------------------------------------------------------------- kernel 2
// Finalize means/weights + pairwise push (distance) term. Single block.
__global__ void k2_mid(float* out) {
    __shared__ int   pres[B_][L_];
    __shared__ float nlsh[B_];
    __shared__ float red[512];
    const int tid = threadIdx.x;

    for (int idx = tid; idx < B_*L_; idx += 512) {
        int b = idx / L_, l = idx % L_;
        pres[b][l] = (l != 0 && g_cnt[b][l] > 0.f) ? 1 : 0;
    }
    __syncthreads();
    if (tid < B_) {
        int nl = 0;
        for (int l = 0; l < L_; l++) nl += pres[tid][l];
        nlsh[tid] = (float)nl;
    }
    __syncthreads();

    for (int idx = tid; idx < B_*L_*D_; idx += 512) {
        int b = idx / (L_*D_);
        int l = (idx / D_) % L_;
        int d = idx % D_;
        float c = fmaxf(g_cnt[b][l], 1.f);
        g_means[b][l][d] = g_sums[b][l][d] / c;
    }
    for (int idx = tid; idx < B_*L_; idx += 512) {
        int b = idx / L_, l = idx % L_;
        float c  = fmaxf(g_cnt[b][l], 1.f);
        float nl = fmaxf(nlsh[b], 1.f);
        g_w[b][l] = pres[b][l] ? (1.f / (c * nl * (float)B_)) : 0.f;
    }
    __syncthreads();   // g_means visible block-wide

    float acc = 0.f;
    for (int idx = tid; idx < B_*L_*L_; idx += 512) {
        int b = idx / (L_*L_);
        int i = (idx / L_) % L_;
        int j = idx % L_;
        if (i != j && pres[b][i] && pres[b][j]) {
            float nl = nlsh[b];
            if (nl > 1.f) {
                float ss = 0.f;
#pragma unroll
                for (int d = 0; d < D_; d++) {
                    float dm = g_means[b][i][d] - g_means[b][j][d];
                    ss = fmaf(dm, dm, ss);
                }
                float dist = sqrtf(ss);
                float p = fmaxf(1.5f - dist, 0.f);
                float denom = fmaxf(nl * (nl - 1.f), 1.f);
                acc += (p * p) / denom * 0.5f / (float)B_;
            }
        }
    }
    red[tid] = acc;
    __syncthreads();
    for (int s = 256; s > 0; s >>= 1) {
        if (tid < s) red[tid] += red[tid + s];
        __syncthreads();
    }
    if (tid == 0) atomicAdd(out, red[0]);
}

// ---------------------------------------------------------------- kernel 3
// Variance (pull) term, pre-weighted so it sums directly into the loss.
// 4 pixels/thread via float4/int4; block 288 -> exactly 2 iterations.
__global__ void __launch_bounds__(288) k3_var(const float* __restrict__ emb,
                                              const int* __restrict__ seg,
                                              float* out) {
    const int b = blockIdx.y;
    __shared__ float sm_m[D_][L_];   // [d][l]: 17-float stride, conflict-free
    __shared__ float sm_w[L_];
    __shared__ float wsum[16];
    const int tid = threadIdx.x;

    for (int idx = tid; idx < D_*L_; idx += 288) {
        int d = idx / L_, l = idx % L_;
        sm_m[d][l] = g_means[b][l][d];
    }
    if (tid < L_) sm_w[tid] = g_w[b][tid];
    if (tid < 16) wsum[tid] = 0.f;
    __syncthreads();

    const int chunk = N_ / CH_;      // 2304 = 2 * 288 * 4
    const int lo    = blockIdx.x * chunk;
    const float* __restrict__ e  = emb + (size_t)b * D_ * N_;
    const int* __restrict__   sp = seg + (size_t)b * N_;

    float acc = 0.f;
#pragma unroll
    for (int half = 0; half < 2; half++) {
        int n = lo + half * (288 * 4) + tid * 4;
        int4 s4 = *(const int4*)(sp + n);
        float4 v[D_];
#pragma unroll
        for (int d = 0; d < D_; d++)
            v[d] = *(const float4*)(e + (size_t)d * N_ + n);

#define PXV(S, COMP)                                                           \
        {                                                                      \
            int s = (S);                                                       \
            float w = sm_w[s];                                                 \
            float ss = 0.f;                                                    \
            _Pragma("unroll")                                                  \
            for (int d = 0; d < D_; d++) {                                     \
                float df = v[d].COMP - sm_m[d][s];                             \
                ss = fmaf(df, df, ss);                                         \
            }                                                                  \
            float nrm = sqrtf(fmaxf(ss, 1e-12f));                              \
            float t = fmaxf(nrm - 0.5f, 0.f);                                  \
            acc = fmaf(w, t * t, acc);                                         \
        }
        PXV(s4.x, x); PXV(s4.y, y); PXV(s4.z, z); PXV(s4.w, w);
#undef PXV
    }
#pragma unroll
    for (int off = 16; off >= 1; off >>= 1)
        acc += __shfl_xor_sync(0xffffffffu, acc, off);
    if ((tid & 31) == 0) wsum[tid >> 5] = acc;
    __syncthreads();
    if (tid < 16) {
        float a = wsum[tid];
#pragma unroll
        for (int off = 8; off >= 1; off >>= 1)
            a += __shfl_xor_sync(0xffffu, a, off);
        if (tid == 0) atomicAdd(out, a);
    }
}

// ---------------------------------------------------------------- launch
extern "C" void kernel_launch(void* const* d_in, const int* in_sizes, int n_in,
                              void* d_out, int out_size) {
    const float* emb = (const float*)d_in[0];
    const int*   seg = (const int*)d_in[1];
    float*       out = (float*)d_out;

    k0_zero<<<8, 256>>>(out);

    dim3 g1(K1CH, B_), b1(32, 8);
    k1_sums<<<g1, b1>>>(emb, seg);

    k2_mid<<<1, 512>>>(out);

    dim3 g3(CH_, B_);
    k3_var<<<g3, 288>>>(emb, seg, out);
}

// round 14
// speedup vs baseline: 1.2352x; 1.2352x over previous
#include <cuda_runtime.h>

#define B_ 16
#define D_ 16
#define H_ 288
#define W_ 512
#define N_ (H_*W_)   // 147456
#define L_ 17
#define CH_ 64       // k3 chunks -> 2304 px/block
#define K1CH 24      // k1 chunks -> 6144 px/block; 384 blocks = ONE wave @3/SM

// persistent scratch (re-zeroed every launch: graph replays reuse it)
__device__ float g_sums[B_][L_][D_];
__device__ float g_cnt[B_][L_];
__device__ float g_means[B_][L_][D_];
__device__ float g_w[B_][L_];

// ---------------------------------------------------------------- kernel 0
__global__ void k0_zero(float* out) {
    int t = blockIdx.x * blockDim.x + threadIdx.x;
    int stride = gridDim.x * blockDim.x;
    if (t == 0) out[0] = 0.f;
    float* s = &g_sums[0][0][0];
    for (int i = t; i < B_*L_*D_; i += stride) s[i] = 0.f;
    float* c = &g_cnt[0][0];
    for (int i = t; i < B_*L_; i += stride) c[i] = 0.f;
}

// ---------------------------------------------------------------- kernel 1
// Per-label sums + counts via per-THREAD indexed smem accumulators (R9
// structure: best measured variant). Block = (32 lanes, 8 warps); warp w
// owns dims 2w, 2w+1. 8 px/thread/iter, 6 front-batched LDG.128 + depth-1
// prefetch. K1CH=24 -> 384 blocks -> exactly one wave at 3 blocks/SM.
__global__ void __launch_bounds__(256, 3) k1_sums(const float* __restrict__ emb,
                                                  const int* __restrict__ seg) {
    __shared__ float ac0[8][32][17];   // [warp][lane][label] dim 2w
    __shared__ float ac1[8][32][17];   // [warp][lane][label] dim 2w+1

    const int b    = blockIdx.y;
    const int lane = threadIdx.x;
    const int w    = threadIdx.y;
    const int chunk = N_ / K1CH;                   // 6144
    const int lo    = blockIdx.x * chunk;
    const int ITERS = chunk / 256;                 // 24 (256 px per warp-iter)

    float* __restrict__ a0 = &ac0[w][lane][0];     // thread-private
    float* __restrict__ a1 = &ac1[w][lane][0];
#pragma unroll
    for (int i = 0; i < 17; i++) { a0[i] = 0.f; a1[i] = 0.f; }

    const float* __restrict__ e0 = emb + ((size_t)b * D_ + 2 * w) * N_;
    const float* __restrict__ e1 = e0 + N_;
    const int*   __restrict__ sp = seg + (size_t)b * N_;

    int cnt[16];
#pragma unroll
    for (int l = 0; l < 16; l++) cnt[l] = 0;

    // depth-1 prefetch: 6 LDG.128 per stage, two dense 128-px groups
    int nA = lo + lane * 4;
    int4   sAx = *(const int4*)(sp + nA);
    int4   sAy = *(const int4*)(sp + nA + 128);
    float4 pA0 = *(const float4*)(e0 + nA);
    float4 pA1 = *(const float4*)(e0 + nA + 128);
    float4 qA0 = *(const float4*)(e1 + nA);
    float4 qA1 = *(const float4*)(e1 + nA + 128);

    for (int it = 0; it < ITERS; ++it) {
        int nn = (it + 1 < ITERS) ? (lo + (it + 1) * 256 + lane * 4) : nA;
        int4   sBx = *(const int4*)(sp + nn);
        int4   sBy = *(const int4*)(sp + nn + 128);
        float4 pB0 = *(const float4*)(e0 + nn);
        float4 pB1 = *(const float4*)(e0 + nn + 128);
        float4 qB0 = *(const float4*)(e1 + nn);
        float4 qB1 = *(const float4*)(e1 + nn + 128);

        // two independent indexed-accumulate chains (dim0 / dim1)
        a0[sAx.x] += pA0.x;  a1[sAx.x] += qA0.x;
        a0[sAx.y] += pA0.y;  a1[sAx.y] += qA0.y;
        a0[sAx.z] += pA0.z;  a1[sAx.z] += qA0.z;
        a0[sAx.w] += pA0.w;  a1[sAx.w] += qA0.w;
        a0[sAy.x] += pA1.x;  a1[sAy.x] += qA1.x;
        a0[sAy.y] += pA1.y;  a1[sAy.y] += qA1.y;
        a0[sAy.z] += pA1.z;  a1[sAy.z] += qA1.z;
        a0[sAy.w] += pA1.w;  a1[sAy.w] += qA1.w;

        // rotating count warp: every iteration counted exactly once
        if (((it - w) & 7) == 0) {
#pragma unroll
            for (int l = 1; l <= 16; l++)
                cnt[l-1] += (sAx.x == l) + (sAx.y == l) + (sAx.z == l) + (sAx.w == l)
                          + (sAy.x == l) + (sAy.y == l) + (sAy.z == l) + (sAy.w == l);
        }

        sAx = sBx; sAy = sBy;
        pA0 = pB0; pA1 = pB1; qA0 = qB0; qA1 = qB1;
    }

    // reduce each thread's private sums across the warp, commit via atomics
#pragma unroll
    for (int s = 1; s < L_; s++) {
        float v0 = a0[s];
        float v1 = a1[s];
#pragma unroll
        for (int off = 16; off >= 1; off >>= 1) {
            v0 += __shfl_xor_sync(0xffffffffu, v0, off);
            v1 += __shfl_xor_sync(0xffffffffu, v1, off);
        }
        if (lane == 0) {
            atomicAdd(&g_sums[b][s][2 * w],     v0);
            atomicAdd(&g_sums[b][s][2 * w + 1], v1);
        }
    }
#pragma unroll
    for (int l = 0; l < 16; l++) {
        int c = cnt[l];
#pragma unroll
        for (int off = 16; off >= 1; off >>= 1)
            c += __shfl_xor_sync(0xffffffffu, c, off);
        if (lane == 0 && c > 0) atomicAdd(&g_cnt[b][l+1], (float)c);
    }
}

// ---------------------------------------------------------------- kernel 2
// Finalize means/weights + pairwise push (distance) term. Single block.
__global__ void k2_mid(float* out) {
    __shared__ int   pres[B_][L_];
    __shared__ float nlsh[B_];
    __shared__ float red[512];
    const int tid = threadIdx.x;

    for (int idx = tid; idx < B_*L_; idx += 512) {
        int b = idx / L_, l = idx % L_;
        pres[b][l] = (l != 0 && g_cnt[b][l] > 0.f) ? 1 : 0;
    }
    __syncthreads();
    if (tid < B_) {
        int nl = 0;
        for (int l = 0; l < L_; l++) nl += pres[tid][l];
        nlsh[tid] = (float)nl;
    }
    __syncthreads();

    for (int idx = tid; idx < B_*L_*D_; idx += 512) {
        int b = idx / (L_*D_);
        int l = (idx / D_) % L_;
        int d = idx % D_;
        float c = fmaxf(g_cnt[b][l], 1.f);
        g_means[b][l][d] = g_sums[b][l][d] / c;
    }
    for (int idx = tid; idx < B_*L_; idx += 512) {
        int b = idx / L_, l = idx % L_;
        float c  = fmaxf(g_cnt[b][l], 1.f);
        float nl = fmaxf(nlsh[b], 1.f);
        g_w[b][l] = pres[b][l] ? (1.f / (c * nl * (float)B_)) : 0.f;
    }
    __syncthreads();   // g_means visible block-wide

    float acc = 0.f;
    for (int idx = tid; idx < B_*L_*L_; idx += 512) {
        int b = idx / (L_*L_);
        int i = (idx / L_) % L_;
        int j = idx % L_;
        if (i != j && pres[b][i] && pres[b][j]) {
            float nl = nlsh[b];
            if (nl > 1.f) {
                float ss = 0.f;
#pragma unroll
                for (int d = 0; d < D_; d++) {
                    float dm = g_means[b][i][d] - g_means[b][j][d];
                    ss = fmaf(dm, dm, ss);
                }
                float dist = sqrtf(ss);
                float p = fmaxf(1.5f - dist, 0.f);
                float denom = fmaxf(nl * (nl - 1.f), 1.f);
                acc += (p * p) / denom * 0.5f / (float)B_;
            }
        }
    }
    red[tid] = acc;
    __syncthreads();
    for (int s = 256; s > 0; s >>= 1) {
        if (tid < s) red[tid] += red[tid + s];
        __syncthreads();
    }
    if (tid == 0) atomicAdd(out, red[0]);
}

// ---------------------------------------------------------------- kernel 3
// Variance (pull) term, pre-weighted so it sums directly into the loss.
// Two 8-dim phases per 4-px group (live float4s halved -> ~60 regs) +
// __launch_bounds__(288,3) -> 3 blocks/SM (27 warps vs 18).
__global__ void __launch_bounds__(288, 3) k3_var(const float* __restrict__ emb,
                                                 const int* __restrict__ seg,
                                                 float* out) {
    const int b = blockIdx.y;
    __shared__ float sm_m[D_][L_];   // [d][l]: 17-float stride, conflict-free
    __shared__ float sm_w[L_];
    __shared__ float wsum[16];
    const int tid = threadIdx.x;

    for (int idx = tid; idx < D_*L_; idx += 288) {
        int d = idx / L_, l = idx % L_;
        sm_m[d][l] = g_means[b][l][d];
    }
    if (tid < L_) sm_w[tid] = g_w[b][tid];
    if (tid < 16) wsum[tid] = 0.f;
    __syncthreads();

    const int chunk = N_ / CH_;      // 2304 = 2 * 288 * 4
    const int lo    = blockIdx.x * chunk;
    const float* __restrict__ e  = emb + (size_t)b * D_ * N_;
    const int* __restrict__   sp = seg + (size_t)b * N_;

    float acc = 0.f;
#pragma unroll
    for (int half = 0; half < 2; half++) {
        int n = lo + half * (288 * 4) + tid * 4;
        int4 s4 = *(const int4*)(sp + n);
        float ssx = 0.f, ssy = 0.f, ssz = 0.f, ssw = 0.f;

#pragma unroll
        for (int ph = 0; ph < 2; ph++) {
            float4 v[8];
#pragma unroll
            for (int d = 0; d < 8; d++)
                v[d] = *(const float4*)(e + (size_t)(ph * 8 + d) * N_ + n);
#pragma unroll
            for (int d = 0; d < 8; d++) {
                const float* mrow = &sm_m[ph * 8 + d][0];
                float dx = v[d].x - mrow[s4.x]; ssx = fmaf(dx, dx, ssx);
                float dy = v[d].y - mrow[s4.y]; ssy = fmaf(dy, dy, ssy);
                float dz = v[d].z - mrow[s4.z]; ssz = fmaf(dz, dz, ssz);
                float dw = v[d].w - mrow[s4.w]; ssw = fmaf(dw, dw, ssw);
            }
        }

#define FIN(SS, S)                                                             \
        {                                                                      \
            float nrm = sqrtf(fmaxf((SS), 1e-12f));                            \
            float t = fmaxf(nrm - 0.5f, 0.f);                                  \
            acc = fmaf(sm_w[S], t * t, acc);                                   \
        }
        FIN(ssx, s4.x); FIN(ssy, s4.y); FIN(ssz, s4.z); FIN(ssw, s4.w);
#undef FIN
    }
#pragma unroll
    for (int off = 16; off >= 1; off >>= 1)
        acc += __shfl_xor_sync(0xffffffffu, acc, off);
    if ((tid & 31) == 0) wsum[tid >> 5] = acc;
    __syncthreads();
    if (tid < 16) {
        float a = wsum[tid];
#pragma unroll
        for (int off = 8; off >= 1; off >>= 1)
            a += __shfl_xor_sync(0xffffu, a, off);
        if (tid == 0) atomicAdd(out, a);
    }
}

// ---------------------------------------------------------------- launch
extern "C" void kernel_launch(void* const* d_in, const int* in_sizes, int n_in,
                              void* d_out, int out_size) {
    const float* emb = (const float*)d_in[0];
    const int*   seg = (const int*)d_in[1];
    float*       out = (float*)d_out;

    k0_zero<<<8, 256>>>(out);

    dim3 g1(K1CH, B_), b1(32, 8);
    k1_sums<<<g1, b1>>>(emb, seg);

    k2_mid<<<1, 512>>>(out);

    dim3 g3(CH_, B_);
    k3_var<<<g3, 288>>>(emb, seg, out);
}